// round 1
// baseline (speedup 1.0000x reference)
#include <cuda_runtime.h>

// ---------------------------------------------------------------------------
// TreeDecoder on GB300 — round 0 baseline.
// Algebraic restructure: Fw0@Fw1 has no nonlinearity between them, so the
// 43-GFLOP dense chain collapses to a precomputed Fcomb[128x128] (2.15 GFLOP
// applied). Total ~5.5 GFLOP fp32.
//
// Inputs (metadata order):
//  0 tree0 [32,1,128]     1 tree1 [32,16,128]   2 tree2 [32,128,128]
//  3 tree3 [32,1024,128]  4 Uw0 [128,128] 5 Ub0[128] 6 Uw1 7 Ub1 8 Uw2 9 Ub2
// 10 Uw3 11 Ub3  12 W_up [1024,128,256]  13 Fw0 [128,1280] 14 Fb0[1280]
// 15 Fw1 [1280,128] 16 Fb1[128] 17 b_bias [1,2048,128]
// Output: float32 [32, 2048, 128]
// ---------------------------------------------------------------------------

#define B_      32
#define CN_     1024
#define F_      128

// Device scratch (no allocations allowed)
__device__ float g_Fcomb[F_ * F_];        // Fw0 @ Fw1
__device__ float g_Fbias[F_];             // Fb0 @ Fw1 + Fb1
__device__ float g_A2[B_ * 128 * F_];     // Q0+Q1+Q2 (+Ub0+Ub1+Ub2) at level-2 (128-node) granularity

// ---------------------------------------------------------------------------
// Kernel 1: Fcomb = Fw0 @ Fw1 ; Fbias = Fb0 @ Fw1 + Fb1
// grid 33 blocks x 128 threads. Blocks 0..31 do 4 rows each; block 32 = bias.
// ---------------------------------------------------------------------------
__global__ void fcomb_kernel(const float* __restrict__ Fw0,
                             const float* __restrict__ Fb0,
                             const float* __restrict__ Fw1,
                             const float* __restrict__ Fb1) {
    __shared__ float f0s[4][1280];
    const int tid = threadIdx.x;   // 0..127 = output column o
    const int blk = blockIdx.x;

    if (blk < 32) {
        for (int idx = tid; idx < 4 * 1280; idx += 128) {
            f0s[idx / 1280][idx % 1280] = Fw0[blk * 4 * 1280 + idx];
        }
        __syncthreads();
        float acc[4] = {0.f, 0.f, 0.f, 0.f};
        #pragma unroll 4
        for (int k = 0; k < 1280; ++k) {
            float w = Fw1[k * 128 + tid];
            #pragma unroll
            for (int r = 0; r < 4; ++r) acc[r] = fmaf(f0s[r][k], w, acc[r]);
        }
        #pragma unroll
        for (int r = 0; r < 4; ++r) g_Fcomb[(blk * 4 + r) * 128 + tid] = acc[r];
    } else {
        float acc = Fb1[tid];
        #pragma unroll 4
        for (int k = 0; k < 1280; ++k)
            acc = fmaf(Fb0[k], Fw1[k * 128 + tid], acc);
        g_Fbias[tid] = acc;
    }
}

// ---------------------------------------------------------------------------
// Kernel 2: A2[b][j2][o] = Q0[b][o] + Q1[b][j2>>3][o] + Q2[b][j2][o]
//                          + Ub0[o] + Ub1[o] + Ub2[o]
// grid = 32 batches * 4 chunks = 128 blocks, 256 threads. Chunk = 32 j2 rows.
// ---------------------------------------------------------------------------
__global__ void a2_kernel(const float* __restrict__ tree0,
                          const float* __restrict__ tree1,
                          const float* __restrict__ tree2,
                          const float* __restrict__ Uw0, const float* __restrict__ Ub0,
                          const float* __restrict__ Uw1, const float* __restrict__ Ub1,
                          const float* __restrict__ Uw2, const float* __restrict__ Ub2) {
    __shared__ float x2s[32][128];   // tree2 chunk
    __shared__ float x1s[4][128];    // tree1 rows covering this chunk
    __shared__ float x0s[128];       // tree0 row
    __shared__ float q01[4][128];    // Q0+Q1 (+biases) for the 4 level-1 rows

    const int b   = blockIdx.x >> 2;
    const int ch  = blockIdx.x & 3;
    const int tid = threadIdx.x;

    for (int idx = tid; idx < 32 * 128; idx += 256) {
        int lr = idx >> 7, k = idx & 127;
        x2s[lr][k] = tree2[(b * 128 + ch * 32 + lr) * 128 + k];
    }
    for (int idx = tid; idx < 4 * 128; idx += 256) {
        int jl = idx >> 7, k = idx & 127;
        x1s[jl][k] = tree1[(b * 16 + ch * 4 + jl) * 128 + k];
    }
    if (tid < 128) x0s[tid] = tree0[b * 128 + tid];
    __syncthreads();

    // q01: 4 rows x 128 cols = 512 outputs over 256 threads (2 each)
    {
        const int o  = tid & 127;
        const int jj = tid >> 7;   // 0 or 1; handles rows jj and jj+2
        float a0 = 0.f, aA = 0.f, aB = 0.f;
        #pragma unroll 4
        for (int k = 0; k < 128; ++k) {
            float w0 = Uw0[k * 128 + o];
            float w1 = Uw1[k * 128 + o];
            a0 = fmaf(x0s[k],        w0, a0);
            aA = fmaf(x1s[jj][k],    w1, aA);
            aB = fmaf(x1s[jj + 2][k], w1, aB);
        }
        float base = a0 + Ub0[o] + Ub1[o] + Ub2[o];
        q01[jj][o]     = aA + base;
        q01[jj + 2][o] = aB + base;
    }
    __syncthreads();

    // GEMM: 32 rows x 128 cols, K=128. Each thread 4x4 tile.
    const int ty = tid >> 5;   // 0..7  -> rows ty*4 .. ty*4+3
    const int tx = tid & 31;   // cols tx + 32*c
    float acc[4][4] = {};
    #pragma unroll 2
    for (int k = 0; k < 128; ++k) {
        float w[4];
        #pragma unroll
        for (int c = 0; c < 4; ++c) w[c] = Uw2[k * 128 + tx + 32 * c];
        #pragma unroll
        for (int r = 0; r < 4; ++r) {
            float a = x2s[ty * 4 + r][k];
            #pragma unroll
            for (int c = 0; c < 4; ++c) acc[r][c] = fmaf(a, w[c], acc[r][c]);
        }
    }
    #pragma unroll
    for (int r = 0; r < 4; ++r) {
        int lr = ty * 4 + r;
        int j2 = ch * 32 + lr;
        #pragma unroll
        for (int c = 0; c < 4; ++c) {
            int col = tx + 32 * c;
            g_A2[(b * 128 + j2) * 128 + col] = acc[r][c] + q01[lr >> 3][col];
        }
    }
}

// ---------------------------------------------------------------------------
// Kernel 3: per-node fused main kernel. grid = 1024 (node n), 256 threads.
//   GEMM1: C1[32][384] = tree3[:,n,:] @ [ W_up[n] (256 cols) | Uw3 (128 cols) ]
//   GEMM2: out64[64][128] = reshape(C1[:, :256]) @ Fcomb
//   epilogue: + tanc (C1[:,256:]) + Ub3 + A2 gather + Fbias + b_bias, LeakyReLU
// Dynamic smem: As 4096 + C1 12288 + Wbuf 6144 floats = 90112 bytes.
// ---------------------------------------------------------------------------
__global__ __launch_bounds__(256, 2)
void main_kernel(const float* __restrict__ tree3,
                 const float* __restrict__ W_up,
                 const float* __restrict__ Uw3,
                 const float* __restrict__ Ub3,
                 const float* __restrict__ b_bias,
                 float* __restrict__ out) {
    extern __shared__ float smem[];
    float* As   = smem;            // [32][128]
    float* C1   = smem + 4096;     // [32][384]
    float* Wbuf = smem + 16384;    // [16][384] (GEMM1) / [16][128] (GEMM2)

    const int n   = blockIdx.x;
    const int tid = threadIdx.x;

    // Load A = tree3[:, n, :]  (32 x 128)
    for (int idx = tid; idx < 4096; idx += 256) {
        int bb = idx >> 7, i = idx & 127;
        As[idx] = tree3[(bb * 1024 + n) * 128 + i];
    }

    // ---- GEMM1: M=32, N=384, K=128 ----
    const int tn = tid & 31;   // col group base
    const int tm = tid >> 5;   // 0..7 -> rows tm*4 .. tm*4+3
    float acc[4][12];
    #pragma unroll
    for (int r = 0; r < 4; ++r)
        #pragma unroll
        for (int j = 0; j < 12; ++j) acc[r][j] = 0.f;

    for (int k0 = 0; k0 < 128; k0 += 16) {
        __syncthreads();  // As ready (1st iter) / previous Wbuf consumers done
        for (int idx = tid; idx < 16 * 384; idx += 256) {
            int kk = idx / 384;
            int c  = idx - kk * 384;
            float v;
            if (c < 256) v = W_up[(n * 128 + k0 + kk) * 256 + c];
            else         v = Uw3[(k0 + kk) * 128 + (c - 256)];
            Wbuf[idx] = v;
        }
        __syncthreads();
        #pragma unroll
        for (int kk = 0; kk < 16; ++kk) {
            float a[4];
            #pragma unroll
            for (int r = 0; r < 4; ++r) a[r] = As[(tm * 4 + r) * 128 + k0 + kk];
            float w[12];
            #pragma unroll
            for (int j = 0; j < 12; ++j) w[j] = Wbuf[kk * 384 + tn + 32 * j];
            #pragma unroll
            for (int r = 0; r < 4; ++r)
                #pragma unroll
                for (int j = 0; j < 12; ++j)
                    acc[r][j] = fmaf(a[r], w[j], acc[r][j]);
        }
    }

    // Write C1
    #pragma unroll
    for (int r = 0; r < 4; ++r)
        #pragma unroll
        for (int j = 0; j < 12; ++j)
            C1[(tm * 4 + r) * 384 + tn + 32 * j] = acc[r][j];
    __syncthreads();

    // ---- GEMM2: 64 rows (b,d) x 128 cols, K=128 (Fcomb) ----
    const int ty = tid >> 5;   // rows ty*8 .. ty*8+7
    const int tx = tid & 31;   // cols tx + 32*c
    float acc2[8][4];
    #pragma unroll
    for (int r = 0; r < 8; ++r)
        #pragma unroll
        for (int c = 0; c < 4; ++c) acc2[r][c] = 0.f;

    for (int k0 = 0; k0 < 128; k0 += 16) {
        for (int idx = tid; idx < 16 * 128; idx += 256)
            Wbuf[idx] = g_Fcomb[k0 * 128 + idx];
        __syncthreads();
        #pragma unroll
        for (int kk = 0; kk < 16; ++kk) {
            float f[4];
            #pragma unroll
            for (int c = 0; c < 4; ++c) f[c] = Wbuf[kk * 128 + tx + 32 * c];
            #pragma unroll
            for (int r = 0; r < 8; ++r) {
                int row = ty * 8 + r;
                float a = C1[(row >> 1) * 384 + (row & 1) * 128 + k0 + kk];
                #pragma unroll
                for (int c = 0; c < 4; ++c)
                    acc2[r][c] = fmaf(a, f[c], acc2[r][c]);
            }
        }
        __syncthreads();  // before next Wbuf overwrite
    }

    // ---- Epilogue ----
    const int j2 = n >> 3;  // level-2 ancestor index
    #pragma unroll
    for (int r = 0; r < 8; ++r) {
        int row = ty * 8 + r;
        int bb  = row >> 1;
        int d   = row & 1;
        int gr  = 2 * n + d;
        #pragma unroll
        for (int c = 0; c < 4; ++c) {
            int col = tx + 32 * c;
            float v = acc2[r][c]
                    + C1[bb * 384 + 256 + col]                 // tree3@Uw3
                    + Ub3[col]
                    + g_A2[(bb * 128 + j2) * 128 + col]        // Q0+Q1+Q2 (+Ub0..2)
                    + g_Fbias[col]                             // Fb0@Fw1 + Fb1
                    + b_bias[gr * 128 + col];
            out[(bb * 2048 + gr) * 128 + col] = (v >= 0.f) ? v : 0.2f * v;
        }
    }
}

// ---------------------------------------------------------------------------
extern "C" void kernel_launch(void* const* d_in, const int* in_sizes, int n_in,
                              void* d_out, int out_size) {
    const float* tree0  = (const float*)d_in[0];
    const float* tree1  = (const float*)d_in[1];
    const float* tree2  = (const float*)d_in[2];
    const float* tree3  = (const float*)d_in[3];
    const float* Uw0    = (const float*)d_in[4];
    const float* Ub0    = (const float*)d_in[5];
    const float* Uw1    = (const float*)d_in[6];
    const float* Ub1    = (const float*)d_in[7];
    const float* Uw2    = (const float*)d_in[8];
    const float* Ub2    = (const float*)d_in[9];
    const float* Uw3    = (const float*)d_in[10];
    const float* Ub3    = (const float*)d_in[11];
    const float* W_up   = (const float*)d_in[12];
    const float* Fw0    = (const float*)d_in[13];
    const float* Fb0    = (const float*)d_in[14];
    const float* Fw1    = (const float*)d_in[15];
    const float* Fb1    = (const float*)d_in[16];
    const float* b_bias = (const float*)d_in[17];
    float* out = (float*)d_out;

    cudaFuncSetAttribute(main_kernel,
                         cudaFuncAttributeMaxDynamicSharedMemorySize, 90112);

    fcomb_kernel<<<33, 128>>>(Fw0, Fb0, Fw1, Fb1);
    a2_kernel<<<128, 256>>>(tree0, tree1, tree2,
                            Uw0, Ub0, Uw1, Ub1, Uw2, Ub2);
    main_kernel<<<1024, 256, 90112>>>(tree3, W_up, Uw3, Ub3, b_bias, out);
}

// round 2
// speedup vs baseline: 1.7434x; 1.7434x over previous
#include <cuda_runtime.h>

// ---------------------------------------------------------------------------
// TreeDecoder on GB300 — round 1.
//  * Fcomb = Fw0@Fw1 now computed split-K (40 blocks) + deterministic reduce
//    (was a 138us latency-bound single-wave kernel).
//  * main_kernel GEMMs use packed fma.rn.f32x2 (FFMA2): 2 FMAs/instr,
//    LDS.64 weight loads, STG.64 output stores.
//
// Inputs (metadata order):
//  0 tree0 [32,1,128]   1 tree1 [32,16,128]  2 tree2 [32,128,128]
//  3 tree3 [32,1024,128] 4..11 Uw0,Ub0..Uw3,Ub3  12 W_up [1024,128,256]
// 13 Fw0 [128,1280] 14 Fb0[1280] 15 Fw1 [1280,128] 16 Fb1[128]
// 17 b_bias [1,2048,128].   Output: float32 [32, 2048, 128]
// ---------------------------------------------------------------------------

#define B_  32
#define F_  128
#define NSPLIT 10

typedef unsigned long long ull;

__device__ __forceinline__ ull dup2(float x) {
    ull r;
    unsigned u = __float_as_uint(x);
    asm("mov.b64 %0, {%1, %1};" : "=l"(r) : "r"(u));
    return r;
}
__device__ __forceinline__ void fma2(ull& d, ull a, ull b) {
    asm("fma.rn.f32x2 %0, %1, %2, %0;" : "+l"(d) : "l"(a), "l"(b));
}
__device__ __forceinline__ float lo32(ull v) { return __uint_as_float((unsigned)v); }
__device__ __forceinline__ float hi32(ull v) { return __uint_as_float((unsigned)(v >> 32)); }

// Device scratch
__device__ float g_Fcomb[F_ * F_];            // Fw0 @ Fw1
__device__ float g_Fbias[F_];                 // Fb0 @ Fw1 + Fb1
__device__ float g_Fpart[NSPLIT * F_ * F_];   // split-K partials
__device__ float g_Fbpart[NSPLIT * F_];       // split-K bias partials
__device__ float g_A2[B_ * 128 * F_];         // Q0+Q1+Q2 (+Ub0..2) at level-2

// ---------------------------------------------------------------------------
// Kernel 1a: split-K partials of Fcomb.
// grid = 10 ksplits * 4 rowtiles = 40 blocks, 256 threads.
// Block (s, rt): rows rt*32..+32 of Fcomb, K slice s*128..+128.
// ---------------------------------------------------------------------------
__global__ void fcomb_part_kernel(const float* __restrict__ Fw0,
                                  const float* __restrict__ Fb0,
                                  const float* __restrict__ Fw1) {
    __shared__ float As[32][128];
    __shared__ float Bs[32][128];

    const int s   = blockIdx.x / 4;
    const int rt  = blockIdx.x & 3;
    const int tid = threadIdx.x;

    // As[r][kk] = Fw0[(rt*32+r)*1280 + s*128 + kk]
    for (int idx = tid; idx < 32 * 128; idx += 256) {
        int r = idx >> 7, kk = idx & 127;
        As[r][kk] = Fw0[(rt * 32 + r) * 1280 + s * 128 + kk];
    }

    const int ty = tid >> 5;   // rows ty*4..
    const int tx = tid & 31;   // cols tx + 32c
    float acc[4][4] = {};
    float bacc = 0.f;

    for (int kb = 0; kb < 128; kb += 32) {
        __syncthreads();
        for (int idx = tid; idx < 32 * 128; idx += 256) {
            int j = idx >> 7, o = idx & 127;
            Bs[j][o] = Fw1[(s * 128 + kb + j) * 128 + o];
        }
        __syncthreads();
        #pragma unroll 8
        for (int j = 0; j < 32; ++j) {
            float w[4];
            #pragma unroll
            for (int c = 0; c < 4; ++c) w[c] = Bs[j][tx + 32 * c];
            #pragma unroll
            for (int r = 0; r < 4; ++r) {
                float a = As[ty * 4 + r][kb + j];
                #pragma unroll
                for (int c = 0; c < 4; ++c) acc[r][c] = fmaf(a, w[c], acc[r][c]);
            }
        }
        if (rt == 0 && tid < 128) {
            #pragma unroll 8
            for (int j = 0; j < 32; ++j)
                bacc = fmaf(Fb0[s * 128 + kb + j], Bs[j][tid], bacc);
        }
    }

    #pragma unroll
    for (int r = 0; r < 4; ++r)
        #pragma unroll
        for (int c = 0; c < 4; ++c)
            g_Fpart[s * 16384 + (rt * 32 + ty * 4 + r) * 128 + tx + 32 * c] = acc[r][c];
    if (rt == 0 && tid < 128) g_Fbpart[s * 128 + tid] = bacc;
}

// ---------------------------------------------------------------------------
// Kernel 1b: deterministic reduce of partials. grid 65 x 256.
// ---------------------------------------------------------------------------
__global__ void fcomb_reduce_kernel(const float* __restrict__ Fb1) {
    const int tid = threadIdx.x;
    if (blockIdx.x < 64) {
        int idx = blockIdx.x * 256 + tid;
        float a = 0.f;
        #pragma unroll
        for (int s = 0; s < NSPLIT; ++s) a += g_Fpart[s * 16384 + idx];
        g_Fcomb[idx] = a;
    } else if (tid < 128) {
        float a = Fb1[tid];
        #pragma unroll
        for (int s = 0; s < NSPLIT; ++s) a += g_Fbpart[s * 128 + tid];
        g_Fbias[tid] = a;
    }
}

// ---------------------------------------------------------------------------
// Kernel 2: A2[b][j2][o] = Q0[b][o] + Q1[b][j2>>3][o] + Q2[b][j2][o]
//                          + Ub0[o] + Ub1[o] + Ub2[o]
// grid = 32 batches * 4 chunks = 128 blocks, 256 threads.
// ---------------------------------------------------------------------------
__global__ void a2_kernel(const float* __restrict__ tree0,
                          const float* __restrict__ tree1,
                          const float* __restrict__ tree2,
                          const float* __restrict__ Uw0, const float* __restrict__ Ub0,
                          const float* __restrict__ Uw1, const float* __restrict__ Ub1,
                          const float* __restrict__ Uw2, const float* __restrict__ Ub2) {
    __shared__ float x2s[32][128];
    __shared__ float x1s[4][128];
    __shared__ float x0s[128];
    __shared__ float q01[4][128];

    const int b   = blockIdx.x >> 2;
    const int ch  = blockIdx.x & 3;
    const int tid = threadIdx.x;

    for (int idx = tid; idx < 32 * 128; idx += 256) {
        int lr = idx >> 7, k = idx & 127;
        x2s[lr][k] = tree2[(b * 128 + ch * 32 + lr) * 128 + k];
    }
    for (int idx = tid; idx < 4 * 128; idx += 256) {
        int jl = idx >> 7, k = idx & 127;
        x1s[jl][k] = tree1[(b * 16 + ch * 4 + jl) * 128 + k];
    }
    if (tid < 128) x0s[tid] = tree0[b * 128 + tid];
    __syncthreads();

    {
        const int o  = tid & 127;
        const int jj = tid >> 7;
        float a0 = 0.f, aA = 0.f, aB = 0.f;
        #pragma unroll 4
        for (int k = 0; k < 128; ++k) {
            float w0 = Uw0[k * 128 + o];
            float w1 = Uw1[k * 128 + o];
            a0 = fmaf(x0s[k],         w0, a0);
            aA = fmaf(x1s[jj][k],     w1, aA);
            aB = fmaf(x1s[jj + 2][k], w1, aB);
        }
        float base = a0 + Ub0[o] + Ub1[o] + Ub2[o];
        q01[jj][o]     = aA + base;
        q01[jj + 2][o] = aB + base;
    }
    __syncthreads();

    const int ty = tid >> 5;
    const int tx = tid & 31;
    float acc[4][4] = {};
    #pragma unroll 2
    for (int k = 0; k < 128; ++k) {
        float w[4];
        #pragma unroll
        for (int c = 0; c < 4; ++c) w[c] = Uw2[k * 128 + tx + 32 * c];
        #pragma unroll
        for (int r = 0; r < 4; ++r) {
            float a = x2s[ty * 4 + r][k];
            #pragma unroll
            for (int c = 0; c < 4; ++c) acc[r][c] = fmaf(a, w[c], acc[r][c]);
        }
    }
    #pragma unroll
    for (int r = 0; r < 4; ++r) {
        int lr = ty * 4 + r;
        int j2 = ch * 32 + lr;
        #pragma unroll
        for (int c = 0; c < 4; ++c) {
            int col = tx + 32 * c;
            g_A2[(b * 128 + j2) * 128 + col] = acc[r][c] + q01[lr >> 3][col];
        }
    }
}

// ---------------------------------------------------------------------------
// Kernel 3: per-node fused main kernel (FFMA2 version). grid = 1024, 256 thr.
//   GEMM1: C1[32][384] = tree3[:,n,:] @ [ W_up[n] | Uw3 ]
//   GEMM2: out64[64][128] = reshape(C1[:, :256]) @ Fcomb
//   epilogue fused.
// Dynamic smem: As 4096 + C1 12288 + Wbuf 6144 floats = 90112 bytes.
// ---------------------------------------------------------------------------
__global__ __launch_bounds__(256, 2)
void main_kernel(const float* __restrict__ tree3,
                 const float* __restrict__ W_up,
                 const float* __restrict__ Uw3,
                 const float* __restrict__ Ub3,
                 const float* __restrict__ b_bias,
                 float* __restrict__ out) {
    extern __shared__ float smem[];
    float* As   = smem;            // [32][128]
    float* C1   = smem + 4096;     // [32][384]
    float* Wbuf = smem + 16384;    // [16][384] / [16][128]

    const int n   = blockIdx.x;
    const int tid = threadIdx.x;

    // Load A = tree3[:, n, :] (32 x 128) with float4 loads
    for (int idx = tid; idx < 1024; idx += 256) {
        int bb = idx >> 5, i4 = (idx & 31) * 4;
        *(float4*)&As[bb * 128 + i4] =
            *(const float4*)&tree3[(bb * 1024 + n) * 128 + i4];
    }

    // ---- GEMM1: M=32, N=384, K=128 ----
    const int tn = tid & 31;   // col pair base: cols tn*2 + 64*j (+0/1)
    const int tm = tid >> 5;   // rows tm*4 .. tm*4+3
    ull acc[4][6];
    #pragma unroll
    for (int r = 0; r < 4; ++r)
        #pragma unroll
        for (int j = 0; j < 6; ++j) acc[r][j] = 0ull;

    for (int k0 = 0; k0 < 128; k0 += 16) {
        __syncthreads();
        // Fill Wbuf [16][384] as float2 (192 pairs/row)
        for (int idx = tid; idx < 16 * 192; idx += 256) {
            int kk = idx / 192;
            int c2 = idx - kk * 192;
            ull v;
            if (c2 < 128)
                v = *(const ull*)&W_up[(n * 128 + k0 + kk) * 256 + c2 * 2];
            else
                v = *(const ull*)&Uw3[(k0 + kk) * 128 + (c2 - 128) * 2];
            *(ull*)&Wbuf[kk * 384 + c2 * 2] = v;
        }
        __syncthreads();
        #pragma unroll
        for (int kk = 0; kk < 16; ++kk) {
            ull ad[4];
            #pragma unroll
            for (int r = 0; r < 4; ++r)
                ad[r] = dup2(As[(tm * 4 + r) * 128 + k0 + kk]);
            ull w[6];
            #pragma unroll
            for (int j = 0; j < 6; ++j)
                w[j] = *(const ull*)&Wbuf[kk * 384 + tn * 2 + 64 * j];
            #pragma unroll
            for (int r = 0; r < 4; ++r)
                #pragma unroll
                for (int j = 0; j < 6; ++j)
                    fma2(acc[r][j], ad[r], w[j]);
        }
    }

    // Write C1 (64-bit stores)
    #pragma unroll
    for (int r = 0; r < 4; ++r)
        #pragma unroll
        for (int j = 0; j < 6; ++j)
            *(ull*)&C1[(tm * 4 + r) * 384 + tn * 2 + 64 * j] = acc[r][j];
    __syncthreads();

    // ---- GEMM2: 64 rows (b,d) x 128 cols, K=128 (Fcomb) ----
    const int ty = tid >> 5;   // rows ty*8 .. ty*8+7
    const int tx = tid & 31;   // cols tx*2 + 64*c (+0/1)
    ull acc2[8][2];
    #pragma unroll
    for (int r = 0; r < 8; ++r) { acc2[r][0] = 0ull; acc2[r][1] = 0ull; }

    for (int k0 = 0; k0 < 128; k0 += 16) {
        // Fill Wbuf [16][128] from g_Fcomb (64-bit loads)
        for (int idx = tid; idx < 1024; idx += 256)
            *(ull*)&Wbuf[idx * 2] = *(const ull*)&g_Fcomb[k0 * 128 + idx * 2];
        __syncthreads();
        #pragma unroll
        for (int kk = 0; kk < 16; ++kk) {
            ull f0 = *(const ull*)&Wbuf[kk * 128 + tx * 2];
            ull f1 = *(const ull*)&Wbuf[kk * 128 + tx * 2 + 64];
            #pragma unroll
            for (int r = 0; r < 8; ++r) {
                int row = ty * 8 + r;
                ull ad = dup2(C1[(row >> 1) * 384 + (row & 1) * 128 + k0 + kk]);
                fma2(acc2[r][0], ad, f0);
                fma2(acc2[r][1], ad, f1);
            }
        }
        __syncthreads();
    }

    // ---- Epilogue (float2 loads/stores) ----
    const int j2 = n >> 3;
    float2 ub[2], fb[2];
    #pragma unroll
    for (int c = 0; c < 2; ++c) {
        int col = tx * 2 + 64 * c;
        ub[c] = *(const float2*)&Ub3[col];
        fb[c] = *(const float2*)&g_Fbias[col];
    }
    #pragma unroll
    for (int r = 0; r < 8; ++r) {
        int row = ty * 8 + r;
        int bb  = row >> 1;
        int d   = row & 1;
        int gr  = 2 * n + d;
        #pragma unroll
        for (int c = 0; c < 2; ++c) {
            int col = tx * 2 + 64 * c;
            float2 t3  = *(const float2*)&C1[bb * 384 + 256 + col];
            float2 a2v = *(const float2*)&g_A2[(bb * 128 + j2) * 128 + col];
            float2 bbv = *(const float2*)&b_bias[gr * 128 + col];
            float vx = lo32(acc2[r][c]) + t3.x + ub[c].x + a2v.x + fb[c].x + bbv.x;
            float vy = hi32(acc2[r][c]) + t3.y + ub[c].y + a2v.y + fb[c].y + bbv.y;
            float2 o;
            o.x = (vx >= 0.f) ? vx : 0.2f * vx;
            o.y = (vy >= 0.f) ? vy : 0.2f * vy;
            *(float2*)&out[(bb * 2048 + gr) * 128 + col] = o;
        }
    }
}

// ---------------------------------------------------------------------------
extern "C" void kernel_launch(void* const* d_in, const int* in_sizes, int n_in,
                              void* d_out, int out_size) {
    const float* tree0  = (const float*)d_in[0];
    const float* tree1  = (const float*)d_in[1];
    const float* tree2  = (const float*)d_in[2];
    const float* tree3  = (const float*)d_in[3];
    const float* Uw0    = (const float*)d_in[4];
    const float* Ub0    = (const float*)d_in[5];
    const float* Uw1    = (const float*)d_in[6];
    const float* Ub1    = (const float*)d_in[7];
    const float* Uw2    = (const float*)d_in[8];
    const float* Ub2    = (const float*)d_in[9];
    const float* Uw3    = (const float*)d_in[10];
    const float* Ub3    = (const float*)d_in[11];
    const float* W_up   = (const float*)d_in[12];
    const float* Fw0    = (const float*)d_in[13];
    const float* Fb0    = (const float*)d_in[14];
    const float* Fw1    = (const float*)d_in[15];
    const float* Fb1    = (const float*)d_in[16];
    const float* b_bias = (const float*)d_in[17];
    float* out = (float*)d_out;

    cudaFuncSetAttribute(main_kernel,
                         cudaFuncAttributeMaxDynamicSharedMemorySize, 90112);

    fcomb_part_kernel<<<40, 256>>>(Fw0, Fb0, Fw1);
    fcomb_reduce_kernel<<<65, 256>>>(Fb1);
    a2_kernel<<<128, 256>>>(tree0, tree1, tree2,
                            Uw0, Ub0, Uw1, Ub1, Uw2, Ub2);
    main_kernel<<<1024, 256, 90112>>>(tree3, W_up, Uw3, Ub3, b_bias, out);
}

// round 3
// speedup vs baseline: 2.7865x; 1.5983x over previous
#include <cuda_runtime.h>
#include <cstdint>

// ---------------------------------------------------------------------------
// TreeDecoder on GB300 — round 2.
//  * main_kernel: cp.async double-buffered weight pipelines (1 barrier/stage,
//    DRAM latency overlapped with FFMA2 compute).
//  * fcomb_part + a2 merged into one prelim launch (concurrent execution).
//
// Inputs (metadata order):
//  0 tree0 [32,1,128]   1 tree1 [32,16,128]  2 tree2 [32,128,128]
//  3 tree3 [32,1024,128] 4..11 Uw0,Ub0..Uw3,Ub3  12 W_up [1024,128,256]
// 13 Fw0 [128,1280] 14 Fb0[1280] 15 Fw1 [1280,128] 16 Fb1[128]
// 17 b_bias [1,2048,128].   Output: float32 [32, 2048, 128]
// ---------------------------------------------------------------------------

#define B_  32
#define F_  128
#define NSPLIT 10

typedef unsigned long long ull;

__device__ __forceinline__ ull dup2(float x) {
    ull r; unsigned u = __float_as_uint(x);
    asm("mov.b64 %0, {%1, %1};" : "=l"(r) : "r"(u));
    return r;
}
__device__ __forceinline__ void fma2(ull& d, ull a, ull b) {
    asm("fma.rn.f32x2 %0, %1, %2, %0;" : "+l"(d) : "l"(a), "l"(b));
}
__device__ __forceinline__ float lo32(ull v) { return __uint_as_float((unsigned)v); }
__device__ __forceinline__ float hi32(ull v) { return __uint_as_float((unsigned)(v >> 32)); }
__device__ __forceinline__ unsigned smem_u32(const void* p) {
    unsigned a;
    asm("{ .reg .u64 t; cvta.to.shared.u64 t, %1; cvt.u32.u64 %0, t; }" : "=r"(a) : "l"(p));
    return a;
}
__device__ __forceinline__ void cp16_cg(unsigned s, const void* g) {
    asm volatile("cp.async.cg.shared.global [%0], [%1], 16;" :: "r"(s), "l"(g));
}
__device__ __forceinline__ void cp16_ca(unsigned s, const void* g) {
    asm volatile("cp.async.ca.shared.global [%0], [%1], 16;" :: "r"(s), "l"(g));
}
#define CP_COMMIT()  asm volatile("cp.async.commit_group;")
#define CP_WAIT0()   asm volatile("cp.async.wait_group 0;")

// Device scratch
__device__ float g_Fcomb[F_ * F_];            // Fw0 @ Fw1
__device__ float g_Fbias[F_];                 // Fb0 @ Fw1 + Fb1
__device__ float g_Fpart[NSPLIT * F_ * F_];   // split-K partials
__device__ float g_Fbpart[NSPLIT * F_];       // split-K bias partials
__device__ float g_A2[B_ * 128 * F_];         // Q0+Q1+Q2 (+Ub0..2) at level-2

// ---------------------------------------------------------------------------
// prelim_kernel: blocks 0..39 = split-K Fcomb partials; blocks 40..167 = A2.
// 256 threads. Unioned smem (8192 floats = 32KB).
// ---------------------------------------------------------------------------
__global__ void prelim_kernel(const float* __restrict__ Fw0,
                              const float* __restrict__ Fb0,
                              const float* __restrict__ Fw1,
                              const float* __restrict__ tree0,
                              const float* __restrict__ tree1,
                              const float* __restrict__ tree2,
                              const float* __restrict__ Uw0, const float* __restrict__ Ub0,
                              const float* __restrict__ Uw1, const float* __restrict__ Ub1,
                              const float* __restrict__ Uw2, const float* __restrict__ Ub2) {
    __shared__ float sh[8192];
    const int tid = threadIdx.x;

    if (blockIdx.x < 40) {
        // ---- Fcomb split-K partial: block (s, rt) ----
        float* As = sh;          // [32][128]
        float* Bs = sh + 4096;   // [32][128]
        const int s  = blockIdx.x / 4;
        const int rt = blockIdx.x & 3;

        for (int idx = tid; idx < 32 * 128; idx += 256) {
            int r = idx >> 7, kk = idx & 127;
            As[r * 128 + kk] = Fw0[(rt * 32 + r) * 1280 + s * 128 + kk];
        }

        const int ty = tid >> 5;
        const int tx = tid & 31;
        float acc[4][4] = {};
        float bacc = 0.f;

        for (int kb = 0; kb < 128; kb += 32) {
            __syncthreads();
            for (int idx = tid; idx < 32 * 128; idx += 256) {
                int j = idx >> 7, o = idx & 127;
                Bs[j * 128 + o] = Fw1[(s * 128 + kb + j) * 128 + o];
            }
            __syncthreads();
            #pragma unroll 8
            for (int j = 0; j < 32; ++j) {
                float w[4];
                #pragma unroll
                for (int c = 0; c < 4; ++c) w[c] = Bs[j * 128 + tx + 32 * c];
                #pragma unroll
                for (int r = 0; r < 4; ++r) {
                    float a = As[(ty * 4 + r) * 128 + kb + j];
                    #pragma unroll
                    for (int c = 0; c < 4; ++c) acc[r][c] = fmaf(a, w[c], acc[r][c]);
                }
            }
            if (rt == 0 && tid < 128) {
                #pragma unroll 8
                for (int j = 0; j < 32; ++j)
                    bacc = fmaf(Fb0[s * 128 + kb + j], Bs[j * 128 + tid], bacc);
            }
        }

        #pragma unroll
        for (int r = 0; r < 4; ++r)
            #pragma unroll
            for (int c = 0; c < 4; ++c)
                g_Fpart[s * 16384 + (rt * 32 + ty * 4 + r) * 128 + tx + 32 * c] = acc[r][c];
        if (rt == 0 && tid < 128) g_Fbpart[s * 128 + tid] = bacc;
    } else {
        // ---- A2: block (b, ch) ----
        float* x2s = sh;          // [32][128]
        float* x1s = sh + 4096;   // [4][128]
        float* x0s = sh + 4608;   // [128]
        float* q01 = sh + 4736;   // [4][128]
        const int bid = blockIdx.x - 40;
        const int b   = bid >> 2;
        const int ch  = bid & 3;

        for (int idx = tid; idx < 32 * 128; idx += 256) {
            int lr = idx >> 7, k = idx & 127;
            x2s[lr * 128 + k] = tree2[(b * 128 + ch * 32 + lr) * 128 + k];
        }
        for (int idx = tid; idx < 4 * 128; idx += 256) {
            int jl = idx >> 7, k = idx & 127;
            x1s[jl * 128 + k] = tree1[(b * 16 + ch * 4 + jl) * 128 + k];
        }
        if (tid < 128) x0s[tid] = tree0[b * 128 + tid];
        __syncthreads();

        {
            const int o  = tid & 127;
            const int jj = tid >> 7;
            float a0 = 0.f, aA = 0.f, aB = 0.f;
            #pragma unroll 4
            for (int k = 0; k < 128; ++k) {
                float w0 = Uw0[k * 128 + o];
                float w1 = Uw1[k * 128 + o];
                a0 = fmaf(x0s[k],              w0, a0);
                aA = fmaf(x1s[jj * 128 + k],   w1, aA);
                aB = fmaf(x1s[(jj + 2) * 128 + k], w1, aB);
            }
            float base = a0 + Ub0[o] + Ub1[o] + Ub2[o];
            q01[jj * 128 + o]       = aA + base;
            q01[(jj + 2) * 128 + o] = aB + base;
        }
        __syncthreads();

        const int ty = tid >> 5;
        const int tx = tid & 31;
        float acc[4][4] = {};
        #pragma unroll 2
        for (int k = 0; k < 128; ++k) {
            float w[4];
            #pragma unroll
            for (int c = 0; c < 4; ++c) w[c] = Uw2[k * 128 + tx + 32 * c];
            #pragma unroll
            for (int r = 0; r < 4; ++r) {
                float a = x2s[(ty * 4 + r) * 128 + k];
                #pragma unroll
                for (int c = 0; c < 4; ++c) acc[r][c] = fmaf(a, w[c], acc[r][c]);
            }
        }
        #pragma unroll
        for (int r = 0; r < 4; ++r) {
            int lr = ty * 4 + r;
            int j2 = ch * 32 + lr;
            #pragma unroll
            for (int c = 0; c < 4; ++c) {
                int col = tx + 32 * c;
                g_A2[(b * 128 + j2) * 128 + col] = acc[r][c] + q01[(lr >> 3) * 128 + col];
            }
        }
    }
}

// ---------------------------------------------------------------------------
// reduce_kernel: deterministic sum of split-K partials. grid 65 x 256.
// ---------------------------------------------------------------------------
__global__ void reduce_kernel(const float* __restrict__ Fb1) {
    const int tid = threadIdx.x;
    if (blockIdx.x < 64) {
        int idx = blockIdx.x * 256 + tid;
        float a = 0.f;
        #pragma unroll
        for (int s = 0; s < NSPLIT; ++s) a += g_Fpart[s * 16384 + idx];
        g_Fcomb[idx] = a;
    } else if (tid < 128) {
        float a = Fb1[tid];
        #pragma unroll
        for (int s = 0; s < NSPLIT; ++s) a += g_Fbpart[s * 128 + tid];
        g_Fbias[tid] = a;
    }
}

// ---------------------------------------------------------------------------
// main_kernel: per-node fused, cp.async double-buffered. grid=1024, 256 thr.
//   GEMM1: C1[32][384] = tree3[:,n,:] @ [ W_up[n] | Uw3 ]   (FFMA2)
//   GEMM2: out64[64][128] = reshape(C1[:, :256]) @ Fcomb    (FFMA2)
// smem: As 4096 + C1 12288 + Wb 2*6144 = 28672 floats = 114688 bytes.
// ---------------------------------------------------------------------------
__global__ __launch_bounds__(256, 2)
void main_kernel(const float* __restrict__ tree3,
                 const float* __restrict__ W_up,
                 const float* __restrict__ Uw3,
                 const float* __restrict__ Ub3,
                 const float* __restrict__ b_bias,
                 float* __restrict__ out) {
    extern __shared__ float smem[];
    float* As = smem;               // [32][128]
    float* C1 = smem + 4096;        // [32][384]
    float* Wb = smem + 16384;       // [2][6144]

    const int n   = blockIdx.x;
    const int tid = threadIdx.x;
    const unsigned wb_u32 = smem_u32(Wb);

    // ---- GEMM1 fill descriptors: 6 x 16B cp.async per thread per stage ----
    // float4 index g = tid + 256*q over [16 rows][96 float4]; kk=g/96, c4=g%96.
    const char* g1src[6];
    int         g1step[6];
    unsigned    g1soff[6];
    #pragma unroll
    for (int q = 0; q < 6; ++q) {
        int g = tid + 256 * q;
        int kk = g / 96, c4 = g - kk * 96;
        if (c4 < 64) {
            g1src[q]  = (const char*)(W_up + ((size_t)n * 128 + kk) * 256 + c4 * 4);
            g1step[q] = 16 * 256 * 4;
        } else {
            g1src[q]  = (const char*)(Uw3 + kk * 128 + (c4 - 64) * 4);
            g1step[q] = 16 * 128 * 4;
        }
        g1soff[q] = (unsigned)(kk * 384 + c4 * 4) * 4;
    }

    // Prologue: issue stage 0 copies (buffer 0)
    #pragma unroll
    for (int q = 0; q < 6; ++q) cp16_cg(wb_u32 + g1soff[q], g1src[q]);
    CP_COMMIT();

    // Load As (float4)
    for (int idx = tid; idx < 1024; idx += 256) {
        int bb = idx >> 5, i4 = (idx & 31) << 2;
        *(float4*)&As[bb * 128 + i4] =
            *(const float4*)&tree3[((size_t)bb * 1024 + n) * 128 + i4];
    }

    const int tn = tid & 31;
    const int tm = tid >> 5;
    ull acc[4][6] = {};

    // ---- GEMM1: 8 stages of K=16 ----
    for (int it = 0; it < 8; ++it) {
        CP_WAIT0();
        __syncthreads();
        if (it < 7) {
            unsigned dst = wb_u32 + (unsigned)(((it + 1) & 1) * 6144 * 4);
            #pragma unroll
            for (int q = 0; q < 6; ++q) {
                g1src[q] += g1step[q];
                cp16_cg(dst + g1soff[q], g1src[q]);
            }
            CP_COMMIT();
        }
        const float* buf = Wb + (it & 1) * 6144;
        const int k0 = it * 16;
        #pragma unroll
        for (int kk = 0; kk < 16; ++kk) {
            ull ad[4];
            #pragma unroll
            for (int r = 0; r < 4; ++r)
                ad[r] = dup2(As[(tm * 4 + r) * 128 + k0 + kk]);
            ull w[6];
            #pragma unroll
            for (int j = 0; j < 6; ++j)
                w[j] = *(const ull*)&buf[kk * 384 + tn * 2 + 64 * j];
            #pragma unroll
            for (int r = 0; r < 4; ++r)
                #pragma unroll
                for (int j = 0; j < 6; ++j)
                    fma2(acc[r][j], ad[r], w[j]);
        }
    }

    // Store C1 (64-bit stores)
    #pragma unroll
    for (int r = 0; r < 4; ++r)
        #pragma unroll
        for (int j = 0; j < 6; ++j)
            *(ull*)&C1[(tm * 4 + r) * 384 + tn * 2 + 64 * j] = acc[r][j];

    // GEMM2 prologue: issue Fcomb stage 0 (buffer 0). Writes buf0, whose last
    // GEMM1 readers (stage 6) are all done (stage-7 barrier).
    {
        const char* src = (const char*)g_Fcomb;
        #pragma unroll
        for (int q = 0; q < 2; ++q)
            cp16_ca(wb_u32 + (unsigned)(tid + 256 * q) * 16, src + (tid + 256 * q) * 16);
        CP_COMMIT();
    }

    const int ty = tid >> 5;
    const int tx = tid & 31;
    ull acc2[8][2] = {};

    // ---- GEMM2: 8 stages of K=16 ----
    for (int it = 0; it < 8; ++it) {
        CP_WAIT0();
        __syncthreads();      // also publishes C1 on it==0
        if (it < 7) {
            unsigned dst = wb_u32 + (unsigned)(((it + 1) & 1) * 6144 * 4);
            const char* src = (const char*)(g_Fcomb + (it + 1) * 2048);
            #pragma unroll
            for (int q = 0; q < 2; ++q)
                cp16_ca(dst + (unsigned)(tid + 256 * q) * 16, src + (tid + 256 * q) * 16);
            CP_COMMIT();
        }
        const float* buf = Wb + (it & 1) * 6144;
        const int k0 = it * 16;
        #pragma unroll
        for (int kk = 0; kk < 16; ++kk) {
            ull f0 = *(const ull*)&buf[kk * 128 + tx * 2];
            ull f1 = *(const ull*)&buf[kk * 128 + tx * 2 + 64];
            #pragma unroll
            for (int r = 0; r < 8; ++r) {
                int row = ty * 8 + r;
                ull ad = dup2(C1[(row >> 1) * 384 + (row & 1) * 128 + k0 + kk]);
                fma2(acc2[r][0], ad, f0);
                fma2(acc2[r][1], ad, f1);
            }
        }
    }

    // ---- Epilogue ----
    const int j2 = n >> 3;
    float2 ub[2], fb[2];
    #pragma unroll
    for (int c = 0; c < 2; ++c) {
        int col = tx * 2 + 64 * c;
        ub[c] = *(const float2*)&Ub3[col];
        fb[c] = *(const float2*)&g_Fbias[col];
    }
    #pragma unroll
    for (int r = 0; r < 8; ++r) {
        int row = ty * 8 + r;
        int bb  = row >> 1;
        int d   = row & 1;
        int gr  = 2 * n + d;
        #pragma unroll
        for (int c = 0; c < 2; ++c) {
            int col = tx * 2 + 64 * c;
            float2 t3  = *(const float2*)&C1[bb * 384 + 256 + col];
            float2 a2v = *(const float2*)&g_A2[(bb * 128 + j2) * 128 + col];
            float2 bbv = *(const float2*)&b_bias[gr * 128 + col];
            float vx = lo32(acc2[r][c]) + t3.x + ub[c].x + a2v.x + fb[c].x + bbv.x;
            float vy = hi32(acc2[r][c]) + t3.y + ub[c].y + a2v.y + fb[c].y + bbv.y;
            float2 o;
            o.x = (vx >= 0.f) ? vx : 0.2f * vx;
            o.y = (vy >= 0.f) ? vy : 0.2f * vy;
            *(float2*)&out[((size_t)bb * 2048 + gr) * 128 + col] = o;
        }
    }
}

// ---------------------------------------------------------------------------
extern "C" void kernel_launch(void* const* d_in, const int* in_sizes, int n_in,
                              void* d_out, int out_size) {
    const float* tree0  = (const float*)d_in[0];
    const float* tree1  = (const float*)d_in[1];
    const float* tree2  = (const float*)d_in[2];
    const float* tree3  = (const float*)d_in[3];
    const float* Uw0    = (const float*)d_in[4];
    const float* Ub0    = (const float*)d_in[5];
    const float* Uw1    = (const float*)d_in[6];
    const float* Ub1    = (const float*)d_in[7];
    const float* Uw2    = (const float*)d_in[8];
    const float* Ub2    = (const float*)d_in[9];
    const float* Uw3    = (const float*)d_in[10];
    const float* Ub3    = (const float*)d_in[11];
    const float* W_up   = (const float*)d_in[12];
    const float* Fw0    = (const float*)d_in[13];
    const float* Fb0    = (const float*)d_in[14];
    const float* Fw1    = (const float*)d_in[15];
    const float* Fb1    = (const float*)d_in[16];
    const float* b_bias = (const float*)d_in[17];
    float* out = (float*)d_out;

    cudaFuncSetAttribute(main_kernel,
                         cudaFuncAttributeMaxDynamicSharedMemorySize, 114688);

    prelim_kernel<<<168, 256>>>(Fw0, Fb0, Fw1,
                                tree0, tree1, tree2,
                                Uw0, Ub0, Uw1, Ub1, Uw2, Ub2);
    reduce_kernel<<<65, 256>>>(Fb1);
    main_kernel<<<1024, 256, 114688>>>(tree3, W_up, Uw3, Ub3, b_bias, out);
}

// round 5
// speedup vs baseline: 3.1341x; 1.1247x over previous
#include <cuda_runtime.h>
#include <cstdint>

// ---------------------------------------------------------------------------
// TreeDecoder on GB300 — round 4 (fixes round-4 Q01 coverage bug).
//  * prelim: Fcomb split-K (40 blk) + Q2 GEMM (128 blk) + Q01 (16 blk x 32 rows).
//  * main: cp.async double-buffered, K=8 stages, 88KB smem -> 2 CTAs/SM.
// ---------------------------------------------------------------------------

#define B_  32
#define F_  128
#define NSPLIT 10

typedef unsigned long long ull;

__device__ __forceinline__ ull dup2(float x) {
    ull r; unsigned u = __float_as_uint(x);
    asm("mov.b64 %0, {%1, %1};" : "=l"(r) : "r"(u));
    return r;
}
__device__ __forceinline__ void fma2(ull& d, ull a, ull b) {
    asm("fma.rn.f32x2 %0, %1, %2, %0;" : "+l"(d) : "l"(a), "l"(b));
}
__device__ __forceinline__ float lo32(ull v) { return __uint_as_float((unsigned)v); }
__device__ __forceinline__ float hi32(ull v) { return __uint_as_float((unsigned)(v >> 32)); }
__device__ __forceinline__ unsigned smem_u32(const void* p) {
    unsigned a;
    asm("{ .reg .u64 t; cvta.to.shared.u64 t, %1; cvt.u32.u64 %0, t; }" : "=r"(a) : "l"(p));
    return a;
}
__device__ __forceinline__ void cp16_cg(unsigned s, const void* g) {
    asm volatile("cp.async.cg.shared.global [%0], [%1], 16;" :: "r"(s), "l"(g));
}
__device__ __forceinline__ void cp16_ca(unsigned s, const void* g) {
    asm volatile("cp.async.ca.shared.global [%0], [%1], 16;" :: "r"(s), "l"(g));
}
#define CP_COMMIT()  asm volatile("cp.async.commit_group;")
#define CP_WAIT0()   asm volatile("cp.async.wait_group 0;")

// Device scratch
__device__ float g_Fcomb[F_ * F_];            // Fw0 @ Fw1
__device__ float g_Fbias[F_];                 // Fb0 @ Fw1 + Fb1
__device__ float g_Fpart[NSPLIT * F_ * F_];   // split-K partials
__device__ float g_Fbpart[NSPLIT * F_];       // split-K bias partials
__device__ float g_A2[B_ * 128 * F_];         // Q2 = tree2_flat @ Uw2
__device__ float g_Q01[B_ * 16 * F_];         // Q0+Q1+Ub0+Ub1+Ub2 per (b,j1)

// ---------------------------------------------------------------------------
// prelim_kernel, 184 blocks x 256 threads, dynamic smem 56KB.
//   blocks 0..39    : Fcomb split-K partials (s = bx/4, rt = bx%4)
//   blocks 40..167  : Q2 GEMM, 32 rows of tree2_flat each
//   blocks 168..183 : Q01, 32 (b,j1) flat rows each (2 batches/block)
// ---------------------------------------------------------------------------
__global__ __launch_bounds__(256)
void prelim_kernel(const float* __restrict__ Fw0,
                   const float* __restrict__ Fb0,
                   const float* __restrict__ Fw1,
                   const float* __restrict__ tree0,
                   const float* __restrict__ tree1,
                   const float* __restrict__ tree2,
                   const float* __restrict__ Uw0, const float* __restrict__ Ub0,
                   const float* __restrict__ Uw1, const float* __restrict__ Ub1,
                   const float* __restrict__ Uw2, const float* __restrict__ Ub2) {
    extern __shared__ float sh[];
    const int tid = threadIdx.x;
    const int bx  = blockIdx.x;
    const int ty  = tid >> 5;
    const int tx  = tid & 31;

    if (bx < 40) {
        // ---- Fcomb split-K partial ----
        float* As = sh;          // [32][128]
        float* Bs = sh + 4096;   // [32][128]
        const int s  = bx >> 2;
        const int rt = bx & 3;

        for (int i4 = tid; i4 < 1024; i4 += 256) {
            int r = i4 >> 5, k4 = (i4 & 31) << 2;
            *(float4*)&As[r * 128 + k4] =
                *(const float4*)&Fw0[(rt * 32 + r) * 1280 + s * 128 + k4];
        }

        float acc[4][4] = {};
        float bacc = 0.f;

        for (int kb = 0; kb < 128; kb += 32) {
            __syncthreads();
            for (int i4 = tid; i4 < 1024; i4 += 256) {
                int j = i4 >> 5, o4 = (i4 & 31) << 2;
                *(float4*)&Bs[j * 128 + o4] =
                    *(const float4*)&Fw1[(s * 128 + kb + j) * 128 + o4];
            }
            __syncthreads();
            #pragma unroll 8
            for (int j = 0; j < 32; ++j) {
                float w[4];
                #pragma unroll
                for (int c = 0; c < 4; ++c) w[c] = Bs[j * 128 + tx + 32 * c];
                #pragma unroll
                for (int r = 0; r < 4; ++r) {
                    float a = As[(ty * 4 + r) * 128 + kb + j];
                    #pragma unroll
                    for (int c = 0; c < 4; ++c) acc[r][c] = fmaf(a, w[c], acc[r][c]);
                }
            }
            if (rt == 0 && tid < 128) {
                #pragma unroll 8
                for (int j = 0; j < 32; ++j)
                    bacc = fmaf(Fb0[s * 128 + kb + j], Bs[j * 128 + tid], bacc);
            }
        }

        #pragma unroll
        for (int r = 0; r < 4; ++r)
            #pragma unroll
            for (int c = 0; c < 4; ++c)
                g_Fpart[s * 16384 + (rt * 32 + ty * 4 + r) * 128 + tx + 32 * c] = acc[r][c];
        if (rt == 0 && tid < 128) g_Fbpart[s * 128 + tid] = bacc;

    } else if (bx < 168) {
        // ---- Q2 GEMM: 32 rows of tree2_flat [4096,128] @ Uw2 -> g_A2 ----
        float* x2s = sh;          // [32][128]
        float* Bs  = sh + 4096;   // [32][128] staged Uw2 chunk
        const int bid = bx - 40;
        const int r0  = bid * 32;

        for (int i4 = tid; i4 < 1024; i4 += 256) {
            int lr = i4 >> 5, k4 = (i4 & 31) << 2;
            *(float4*)&x2s[lr * 128 + k4] =
                *(const float4*)&tree2[(r0 + lr) * 128 + k4];
        }

        float acc[4][4] = {};
        for (int kb = 0; kb < 128; kb += 32) {
            __syncthreads();
            for (int i4 = tid; i4 < 1024; i4 += 256) {
                int j = i4 >> 5, o4 = (i4 & 31) << 2;
                *(float4*)&Bs[j * 128 + o4] =
                    *(const float4*)&Uw2[(kb + j) * 128 + o4];
            }
            __syncthreads();
            #pragma unroll 8
            for (int j = 0; j < 32; ++j) {
                float w[4];
                #pragma unroll
                for (int c = 0; c < 4; ++c) w[c] = Bs[j * 128 + tx + 32 * c];
                #pragma unroll
                for (int r = 0; r < 4; ++r) {
                    float a = x2s[(ty * 4 + r) * 128 + kb + j];
                    #pragma unroll
                    for (int c = 0; c < 4; ++c) acc[r][c] = fmaf(a, w[c], acc[r][c]);
                }
            }
        }
        #pragma unroll
        for (int r = 0; r < 4; ++r)
            #pragma unroll
            for (int c = 0; c < 4; ++c)
                g_A2[(r0 + ty * 4 + r) * 128 + tx + 32 * c] = acc[r][c];

    } else {
        // ---- Q01: 32 flat (b,j1) rows per block, 16 blocks ----
        float* t1s   = sh;            // [32][32]
        float* w1s   = sh + 1024;     // [32][128]
        float* w0s   = sh + 5120;     // [32][128]
        float* t0s   = sh + 9216;     // [2][32]
        float* q0buf = sh + 9280;     // [2][128]
        const int q  = bx - 168;      // 0..15
        const int g0 = q * 32;        // flat row base; batches q*2, q*2+1

        float acc[4][4] = {};         // Q1: 32x128 tile
        float q0a = 0.f;              // Q0: one output per thread over [2][128]
        const int q0row = tid >> 7;   // 0..1
        const int q0col = tid & 127;

        for (int kb = 0; kb < 128; kb += 32) {
            __syncthreads();
            {   // t1s: 32 rows x 8 float4 = 256 float4, one per thread
                int row = tid >> 3, k4 = (tid & 7) << 2;
                *(float4*)&t1s[row * 32 + k4] =
                    *(const float4*)&tree1[(g0 + row) * 128 + kb + k4];
            }
            for (int i4 = tid; i4 < 1024; i4 += 256) {
                int j = i4 >> 5, o4 = (i4 & 31) << 2;
                *(float4*)&w1s[j * 128 + o4] =
                    *(const float4*)&Uw1[(kb + j) * 128 + o4];
                *(float4*)&w0s[j * 128 + o4] =
                    *(const float4*)&Uw0[(kb + j) * 128 + o4];
            }
            if (tid < 16) {
                int row = tid >> 3, k4 = (tid & 7) << 2;
                *(float4*)&t0s[row * 32 + k4] =
                    *(const float4*)&tree0[(q * 2 + row) * 128 + kb + k4];
            }
            __syncthreads();
            // Q1: 32x128, K chunk 32
            #pragma unroll 8
            for (int j = 0; j < 32; ++j) {
                float w[4];
                #pragma unroll
                for (int c = 0; c < 4; ++c) w[c] = w1s[j * 128 + tx + 32 * c];
                #pragma unroll
                for (int r = 0; r < 4; ++r) {
                    float a = t1s[(ty * 4 + r) * 32 + j];
                    #pragma unroll
                    for (int c = 0; c < 4; ++c) acc[r][c] = fmaf(a, w[c], acc[r][c]);
                }
            }
            // Q0: [2][128], one output/thread
            #pragma unroll 8
            for (int j = 0; j < 32; ++j)
                q0a = fmaf(t0s[q0row * 32 + j], w0s[j * 128 + q0col], q0a);
        }
        __syncthreads();
        q0buf[tid] = q0a;
        __syncthreads();

        #pragma unroll
        for (int r = 0; r < 4; ++r) {
            int row = ty * 4 + r;          // local row 0..31
            int bl  = row >> 4;            // local batch 0..1
            #pragma unroll
            for (int c = 0; c < 4; ++c) {
                int col = tx + 32 * c;
                g_Q01[(g0 + row) * 128 + col] =
                    acc[r][c] + q0buf[bl * 128 + col]
                    + Ub0[col] + Ub1[col] + Ub2[col];
            }
        }
    }
}

// ---------------------------------------------------------------------------
// reduce_kernel: deterministic sum of split-K partials. grid 65 x 256.
// ---------------------------------------------------------------------------
__global__ void reduce_kernel(const float* __restrict__ Fb1) {
    const int tid = threadIdx.x;
    if (blockIdx.x < 64) {
        int idx = blockIdx.x * 256 + tid;
        float a = 0.f;
        #pragma unroll
        for (int s = 0; s < NSPLIT; ++s) a += g_Fpart[s * 16384 + idx];
        g_Fcomb[idx] = a;
    } else if (tid < 128) {
        float a = Fb1[tid];
        #pragma unroll
        for (int s = 0; s < NSPLIT; ++s) a += g_Fbpart[s * 128 + tid];
        g_Fbias[tid] = a;
    }
}

// ---------------------------------------------------------------------------
// main_kernel: per-node fused, cp.async double-buffered, K=8 stages.
// smem: As 4096 + C1 12288 + Wb 2*3072 = 22528 floats = 90112 B -> 2 CTAs/SM.
// ---------------------------------------------------------------------------
__global__ __launch_bounds__(256, 2)
void main_kernel(const float* __restrict__ tree3,
                 const float* __restrict__ W_up,
                 const float* __restrict__ Uw3,
                 const float* __restrict__ Ub3,
                 const float* __restrict__ b_bias,
                 float* __restrict__ out) {
    extern __shared__ float smem[];
    float* As = smem;               // [32][128]
    float* C1 = smem + 4096;        // [32][384]
    float* Wb = smem + 16384;       // [2][3072]

    const int n   = blockIdx.x;
    const int tid = threadIdx.x;
    const unsigned wb_u32 = smem_u32(Wb);

    // GEMM1 fill: 3 x 16B per thread per stage over [8 rows][96 float4]
    const char* g1src[3];
    int         g1step[3];
    unsigned    g1soff[3];
    #pragma unroll
    for (int q = 0; q < 3; ++q) {
        int g = tid + 256 * q;
        int kk = g / 96, c4 = g - kk * 96;
        if (c4 < 64) {
            g1src[q]  = (const char*)(W_up + ((size_t)n * 128 + kk) * 256 + c4 * 4);
            g1step[q] = 8 * 256 * 4;
        } else {
            g1src[q]  = (const char*)(Uw3 + kk * 128 + (c4 - 64) * 4);
            g1step[q] = 8 * 128 * 4;
        }
        g1soff[q] = (unsigned)(kk * 384 + c4 * 4) * 4;
    }

    // Prologue: stage 0 into buffer 0
    #pragma unroll
    for (int q = 0; q < 3; ++q) cp16_cg(wb_u32 + g1soff[q], g1src[q]);
    CP_COMMIT();

    // Load As (float4)
    for (int idx = tid; idx < 1024; idx += 256) {
        int bb = idx >> 5, i4 = (idx & 31) << 2;
        *(float4*)&As[bb * 128 + i4] =
            *(const float4*)&tree3[((size_t)bb * 1024 + n) * 128 + i4];
    }

    const int tn = tid & 31;
    const int tm = tid >> 5;
    ull acc[4][6] = {};

    // ---- GEMM1: 16 stages of K=8 ----
    for (int it = 0; it < 16; ++it) {
        CP_WAIT0();
        __syncthreads();
        if (it < 15) {
            unsigned dst = wb_u32 + (unsigned)(((it + 1) & 1) * 3072 * 4);
            #pragma unroll
            for (int q = 0; q < 3; ++q) {
                g1src[q] += g1step[q];
                cp16_cg(dst + g1soff[q], g1src[q]);
            }
            CP_COMMIT();
        }
        const float* buf = Wb + (it & 1) * 3072;
        const int k0 = it * 8;
        #pragma unroll
        for (int kk = 0; kk < 8; ++kk) {
            ull ad[4];
            #pragma unroll
            for (int r = 0; r < 4; ++r)
                ad[r] = dup2(As[(tm * 4 + r) * 128 + k0 + kk]);
            ull w[6];
            #pragma unroll
            for (int j = 0; j < 6; ++j)
                w[j] = *(const ull*)&buf[kk * 384 + tn * 2 + 64 * j];
            #pragma unroll
            for (int r = 0; r < 4; ++r)
                #pragma unroll
                for (int j = 0; j < 6; ++j)
                    fma2(acc[r][j], ad[r], w[j]);
        }
    }

    // Store C1
    #pragma unroll
    for (int r = 0; r < 4; ++r)
        #pragma unroll
        for (int j = 0; j < 6; ++j)
            *(ull*)&C1[(tm * 4 + r) * 384 + tn * 2 + 64 * j] = acc[r][j];

    // GEMM2 prologue: Fcomb stage 0 into buffer 0 (buf0's last GEMM1 readers
    // were stage 14, complete before the stage-15 barrier).
    cp16_ca(wb_u32 + (unsigned)tid * 16, (const char*)g_Fcomb + tid * 16);
    CP_COMMIT();

    const int ty = tid >> 5;
    const int tx = tid & 31;
    ull acc2[8][2] = {};

    // ---- GEMM2: 16 stages of K=8 ----
    for (int it = 0; it < 16; ++it) {
        CP_WAIT0();
        __syncthreads();      // also publishes C1 on it==0
        if (it < 15) {
            unsigned dst = wb_u32 + (unsigned)(((it + 1) & 1) * 3072 * 4);
            cp16_ca(dst + (unsigned)tid * 16,
                    (const char*)(g_Fcomb + (it + 1) * 1024) + tid * 16);
            CP_COMMIT();
        }
        const float* buf = Wb + (it & 1) * 3072;
        const int k0 = it * 8;
        #pragma unroll
        for (int kk = 0; kk < 8; ++kk) {
            ull f0 = *(const ull*)&buf[kk * 128 + tx * 2];
            ull f1 = *(const ull*)&buf[kk * 128 + tx * 2 + 64];
            #pragma unroll
            for (int r = 0; r < 8; ++r) {
                int row = ty * 8 + r;
                ull ad = dup2(C1[(row >> 1) * 384 + (row & 1) * 128 + k0 + kk]);
                fma2(acc2[r][0], ad, f0);
                fma2(acc2[r][1], ad, f1);
            }
        }
    }

    // ---- Epilogue ----
    const int j2 = n >> 3;
    const int j1 = n >> 6;
    float2 ub[2], fb[2];
    #pragma unroll
    for (int c = 0; c < 2; ++c) {
        int col = tx * 2 + 64 * c;
        ub[c] = *(const float2*)&Ub3[col];
        fb[c] = *(const float2*)&g_Fbias[col];
    }
    #pragma unroll
    for (int r = 0; r < 8; ++r) {
        int row = ty * 8 + r;
        int bb  = row >> 1;
        int d   = row & 1;
        int gr  = 2 * n + d;
        #pragma unroll
        for (int c = 0; c < 2; ++c) {
            int col = tx * 2 + 64 * c;
            float2 t3  = *(const float2*)&C1[bb * 384 + 256 + col];
            float2 a2v = *(const float2*)&g_A2[(bb * 128 + j2) * 128 + col];
            float2 q01 = *(const float2*)&g_Q01[(bb * 16 + j1) * 128 + col];
            float2 bbv = *(const float2*)&b_bias[gr * 128 + col];
            float vx = lo32(acc2[r][c]) + t3.x + ub[c].x + a2v.x + q01.x + fb[c].x + bbv.x;
            float vy = hi32(acc2[r][c]) + t3.y + ub[c].y + a2v.y + q01.y + fb[c].y + bbv.y;
            float2 o;
            o.x = (vx >= 0.f) ? vx : 0.2f * vx;
            o.y = (vy >= 0.f) ? vy : 0.2f * vy;
            *(float2*)&out[((size_t)bb * 2048 + gr) * 128 + col] = o;
        }
    }
}

// ---------------------------------------------------------------------------
extern "C" void kernel_launch(void* const* d_in, const int* in_sizes, int n_in,
                              void* d_out, int out_size) {
    const float* tree0  = (const float*)d_in[0];
    const float* tree1  = (const float*)d_in[1];
    const float* tree2  = (const float*)d_in[2];
    const float* tree3  = (const float*)d_in[3];
    const float* Uw0    = (const float*)d_in[4];
    const float* Ub0    = (const float*)d_in[5];
    const float* Uw1    = (const float*)d_in[6];
    const float* Ub1    = (const float*)d_in[7];
    const float* Uw2    = (const float*)d_in[8];
    const float* Ub2    = (const float*)d_in[9];
    const float* Uw3    = (const float*)d_in[10];
    const float* Ub3    = (const float*)d_in[11];
    const float* W_up   = (const float*)d_in[12];
    const float* Fw0    = (const float*)d_in[13];
    const float* Fb0    = (const float*)d_in[14];
    const float* Fw1    = (const float*)d_in[15];
    const float* Fb1    = (const float*)d_in[16];
    const float* b_bias = (const float*)d_in[17];
    float* out = (float*)d_out;

    cudaFuncSetAttribute(prelim_kernel,
                         cudaFuncAttributeMaxDynamicSharedMemorySize, 57344);
    cudaFuncSetAttribute(main_kernel,
                         cudaFuncAttributeMaxDynamicSharedMemorySize, 90112);

    prelim_kernel<<<184, 256, 57344>>>(Fw0, Fb0, Fw1,
                                       tree0, tree1, tree2,
                                       Uw0, Ub0, Uw1, Ub1, Uw2, Ub2);
    reduce_kernel<<<65, 256>>>(Fb1);
    main_kernel<<<1024, 256, 90112>>>(tree3, W_up, Uw3, Ub3, b_bias, out);
}